// round 10
// baseline (speedup 1.0000x reference)
#include <cuda_runtime.h>
#include <cstdint>

// UniformShardedEmbeddingBags: B=1024, T=32, D=64, E=100000, L=50
// out[bag, :] = sum_{j<50} W[feat[bag*50 + j], bag % 32, :]
//
// R10 = confirmation re-bench of R8, the best-profiled configuration
// (ncu: 58.0us, DRAM 75.6%, 5989 GB/s). Byte-identical to R8.
//
// Final design (established R2..R9):
//  - one bag per warp; 32 lanes x float2 = 256B fully-coalesced per row;
//    fully-unrolled 25x LDG.64 gather (no persistent loop — R6 showed it
//    breaks ptxas LDG front-batching); 32-reg budget (R4: regs>32 costs
//    occupancy and DRAM util); 128-thread CTAs (R8: best spread/tail).
//  - table-grouped bag order: warps [t*1024,(t+1)*1024) pool table t, so
//    ~9 table slices (~94MB) stay L2-resident and all ~22% duplicate draws
//    hit L2 -> DRAM traffic at the compulsory ~348MB floor.
//  - __stcs output (8MB of writes must not evict gather lines); plain
//    cached index loads (R5: streaming hints on shared index lines hurt).
//  - Remaining gap to 100% DRAM = controller ceiling for random 256B
//    bursts over an 819MB footprint; not addressable from the SM side.

namespace {
constexpr int kT = 32;
constexpr int kD = 64;
constexpr int kL = 50;
constexpr int kNumBags = 1024 * kT;                  // 32768
constexpr int kThreads = 128;                        // 4 warps / block
constexpr int kBlocks = kNumBags / (kThreads / 32);  // 8192
}  // namespace

__global__ __launch_bounds__(kThreads)
void embedding_bag_kernel(const float* __restrict__ weights,
                          const int* __restrict__ features,
                          float* __restrict__ out) {
    const int w = (blockIdx.x * kThreads + threadIdx.x) >> 5;
    const int lane = threadIdx.x & 31;

    // Table-grouped remap: warps [t*1024, (t+1)*1024) all pool table t.
    const int bag = ((w & 1023) << 5) | (w >> 10);
    const int table = w >> 10;  // == bag & 31

    const int* __restrict__ idxp = features + bag * kL;

    // Coalesced index fetch: lane j holds draw j; lanes 0..17 also draw 32+j.
    const int i0 = __ldg(idxp + lane);
    const int i1 = (lane < kL - 32) ? __ldg(idxp + 32 + lane) : 0;

    // Base pointer into this bag's table slice, as float2.
    const float2* __restrict__ base =
        reinterpret_cast<const float2*>(weights) + (size_t)table * (kD / 2);
    constexpr size_t kRowStride2 = (size_t)kT * kD / 2;  // 1024 float2 per e

    float2 acc0 = make_float2(0.f, 0.f);
    float2 acc1 = make_float2(0.f, 0.f);

#pragma unroll
    for (int k = 0; k < 32; k += 2) {
        const int ia = __shfl_sync(0xffffffffu, i0, k);
        const int ib = __shfl_sync(0xffffffffu, i0, k + 1);
        const float2 va = __ldg(base + (size_t)ia * kRowStride2 + lane);
        const float2 vb = __ldg(base + (size_t)ib * kRowStride2 + lane);
        acc0.x += va.x; acc0.y += va.y;
        acc1.x += vb.x; acc1.y += vb.y;
    }
#pragma unroll
    for (int k = 0; k < 18; k += 2) {
        const int ia = __shfl_sync(0xffffffffu, i1, k);
        const int ib = __shfl_sync(0xffffffffu, i1, k + 1);
        const float2 va = __ldg(base + (size_t)ia * kRowStride2 + lane);
        const float2 vb = __ldg(base + (size_t)ib * kRowStride2 + lane);
        acc0.x += va.x; acc0.y += va.y;
        acc1.x += vb.x; acc1.y += vb.y;
    }

    float2 r;
    r.x = acc0.x + acc1.x;
    r.y = acc0.y + acc1.y;
    __stcs(reinterpret_cast<float2*>(out) + (size_t)bag * (kD / 2) + lane, r);
}

extern "C" void kernel_launch(void* const* d_in, const int* in_sizes, int n_in,
                              void* d_out, int out_size) {
    const float* weights  = (const float*)d_in[0];   // (E, T, D) fp32
    const int*   features = (const int*)d_in[1];     // (B*T*L,) int32
    // d_in[2]: offsets — uniform arange*L, folded into compile-time constants.
    float* out = (float*)d_out;                      // (B, T, D) fp32

    embedding_bag_kernel<<<kBlocks, kThreads>>>(weights, features, out);
}